// round 12
// baseline (speedup 1.0000x reference)
#include <cuda_runtime.h>
#include <cuda_bf16.h>

// Problem constants
#define C_DIM 3
#define H_DIM 32
#define W_DIM 32
#define Z_DIM 256
#define NTOK (128 * 1024)             // 131072 tokens
#define NBINS (C_DIM * H_DIM * W_DIM) // 3072 bins
#define CAP 192                       // max valid tokens per bin (mean ~21)
#define RC 32                         // register-cached rows per bin
#define PADBLKS 4096                  // extra blocks for zeroing masked rows
#define EPS 1e-6f
#define MAX_VAL 5.0f
#define MIN_VAL (-5.0f)

// mask: 32-bit word per token (bool promoted by harness); nonzero == padded.

// ---------------- device scratch (static; no allocations allowed) ----------
// d_count starts zeroed (static init) and is re-zeroed by k_fused each launch.
__device__ int d_count[NBINS];
__device__ int d_tokenlist[NBINS * CAP];

// ---------------- K1: direct scatter into fixed-capacity bin slots ---------
__global__ void k_scatter(const int* __restrict__ pc,
                          const int* __restrict__ ph,
                          const int* __restrict__ pw,
                          const unsigned int* __restrict__ mask) {
    int i = blockIdx.x * blockDim.x + threadIdx.x;
    if (i >= NTOK) return;
    if (mask[i] == 0u) {
        int flat = pc[i] * (H_DIM * W_DIM) + ph[i] * W_DIM + pw[i];
        int pos = atomicAdd(&d_count[flat], 1);
        if (pos < CAP) d_tokenlist[flat * CAP + pos] = i;
    }
}

// ---------------- K2: fused stats + normalize + pad-zero -------------------
// blocks [0, NBINS):      one block per bin, thread z owns feature z.
//   fill register cache (first RC rows) with one burst of independent loads,
//   reduce S1,S2, then normalize from the cache; spill to L2 re-reads only
//   for the rare bins with cnt > RC. Bin block zeroes d_count[b] at the end.
// blocks [NBINS, +PADBLKS): grid-stride zero-fill of masked token rows.
__global__ __launch_bounds__(256) void k_fused(
        const float* __restrict__ patches,
        const unsigned int* __restrict__ mask,
        const float* __restrict__ n_buf,
        const float* __restrict__ mean_in,
        const float* __restrict__ m2_in,
        float* __restrict__ out) {
    int tid = threadIdx.x;

    if (blockIdx.x >= NBINS) {
        // ---- pad-zero path: zero all masked rows (float4 granularity) ----
        long long nslots = (long long)NTOK * (Z_DIM / 4);
        long long start = (long long)(blockIdx.x - NBINS) * 256 + tid;
        long long stride = (long long)PADBLKS * 256;
        float4* out4 = (float4*)out;
        for (long long s = start; s < nslots; s += stride) {
            int tok = (int)(s >> 6);
            if (mask[tok] != 0u)
                out4[s] = make_float4(0.f, 0.f, 0.f, 0.f);
        }
        return;
    }

    // ---- per-bin stats + normalize path ----
    __shared__ int s_tok[CAP];
    int b = blockIdx.x;
    int cnt_raw = d_count[b];
    int cnt = cnt_raw < CAP ? cnt_raw : CAP;
    if (tid < cnt) s_tok[tid] = d_tokenlist[b * CAP + tid];
    __syncthreads();
    if (tid == 0) d_count[b] = 0;   // self-zero for next launch/replay

    int z = tid;
    int idx = b * Z_DIM + z;
    float mean_old = mean_in[idx];

    // burst-fill register cache: up to RC independent loads in flight
    float cache[RC];
    #pragma unroll
    for (int k = 0; k < RC; k++) {
        cache[k] = (k < cnt) ? patches[s_tok[k] * Z_DIM + z] : 0.0f;
    }

    float s1 = 0.0f, s2 = 0.0f;
    #pragma unroll
    for (int k = 0; k < RC; k++) {
        if (k < cnt) {
            float e = cache[k] - mean_old;
            s1 += e;
            s2 += e * e;
        }
    }
    // rare spill path (cnt > RC)
    for (int k = RC; k < cnt; k++) {
        float e = patches[s_tok[k] * Z_DIM + z] - mean_old;
        s1 += e;
        s2 += e * e;
    }

    float n_new = n_buf[b] + (float)cnt_raw;
    float nden  = fmaxf(n_new, 1.0f);
    float d     = s1 / nden;
    float mean_new = mean_old + d;
    float m2_new   = m2_in[idx] + (s2 - d * s1);
    float var = m2_new / nden;
    if (n_new < 2.0f) var = 1.0f;
    float inv = 1.0f / (sqrtf(var) + EPS);

    // normalize from the register cache and write out
    #pragma unroll
    for (int k = 0; k < RC; k++) {
        if (k < cnt) {
            float r = fminf(fmaxf((cache[k] - mean_new) * inv, MIN_VAL), MAX_VAL);
            out[s_tok[k] * Z_DIM + z] = r;
        }
    }
    for (int k = RC; k < cnt; k++) {
        float p = patches[s_tok[k] * Z_DIM + z];
        out[s_tok[k] * Z_DIM + z] =
            fminf(fmaxf((p - mean_new) * inv, MIN_VAL), MAX_VAL);
    }
}

// ---------------- launch ----------------------------------------------------
extern "C" void kernel_launch(void* const* d_in, const int* in_sizes, int n_in,
                              void* d_out, int out_size) {
    const float*        patches = (const float*)d_in[0];
    const int*          pc      = (const int*)d_in[1];
    const int*          ph      = (const int*)d_in[2];
    const int*          pw      = (const int*)d_in[3];
    const unsigned int* mask    = (const unsigned int*)d_in[4];
    const float*        n_buf   = (const float*)d_in[5];
    const float*        mean_in = (const float*)d_in[6];
    const float*        m2_in   = (const float*)d_in[7];
    float*              out     = (float*)d_out;

    k_scatter<<<(NTOK + 255) / 256, 256>>>(pc, ph, pw, mask);
    k_fused<<<NBINS + PADBLKS, 256>>>(patches, mask, n_buf, mean_in, m2_in, out);
}

// round 14
// speedup vs baseline: 1.1654x; 1.1654x over previous
#include <cuda_runtime.h>
#include <cuda_bf16.h>

// Problem constants
#define C_DIM 3
#define H_DIM 32
#define W_DIM 32
#define Z_DIM 256
#define NTOK (128 * 1024)             // 131072 tokens
#define NBINS (C_DIM * H_DIM * W_DIM) // 3072 bins
#define CAP 192                       // max valid tokens per bin (mean ~21)
#define PADBLKS 1024                  // pad-zero blocks (4 warps each)
#define EPS 1e-6f
#define MAX_VAL 5.0f
#define MIN_VAL (-5.0f)

// mask: 32-bit word per token (bool promoted by harness); nonzero == padded.

// ---------------- device scratch (static; no allocations allowed) ----------
// d_count starts zeroed (static init) and is re-zeroed by k_fused each launch.
__device__ int d_count[NBINS];
__device__ int d_tokenlist[NBINS * CAP];

// ---------------- K1: direct scatter into fixed-capacity bin slots ---------
__global__ void k_scatter(const int* __restrict__ pc,
                          const int* __restrict__ ph,
                          const int* __restrict__ pw,
                          const unsigned int* __restrict__ mask) {
    int i = blockIdx.x * blockDim.x + threadIdx.x;
    if (i >= NTOK) return;
    if (mask[i] == 0u) {
        int flat = pc[i] * (H_DIM * W_DIM) + ph[i] * W_DIM + pw[i];
        int pos = atomicAdd(&d_count[flat], 1);
        if (pos < CAP) d_tokenlist[flat * CAP + pos] = i;
    }
}

// ---------------- K2: fused stats + normalize + pad-zero -------------------
// 128-thread blocks.
// blocks [0, NBINS): one block per bin; thread owns 2 features (float2).
//   pass 1: reduce S1,S2 over bin's valid rows (DRAM read, x4 unroll)
//   pass 2: re-read rows (L2-hot) and write normalized output
// blocks [NBINS, +PADBLKS): warp-per-32-token ballot scan; cooperative 1KB
//   zero-fill for each padded token.
__global__ __launch_bounds__(128) void k_fused(
        const float* __restrict__ patches,
        const unsigned int* __restrict__ mask,
        const float* __restrict__ n_buf,
        const float* __restrict__ mean_in,
        const float* __restrict__ m2_in,
        float* __restrict__ out) {
    int tid = threadIdx.x;

    if (blockIdx.x >= NBINS) {
        // ---- pad-zero path ----
        int warp = (blockIdx.x - NBINS) * 4 + (tid >> 5); // global warp id
        int lane = tid & 31;
        int tok0 = warp * 32;                              // 32 tokens per warp
        if (tok0 >= NTOK) return;
        unsigned int m = mask[tok0 + lane];
        unsigned int bal = __ballot_sync(0xFFFFFFFFu, m != 0u);
        float4 zero4 = make_float4(0.f, 0.f, 0.f, 0.f);
        float4* out4 = (float4*)out;
        while (bal) {
            int bit = __ffs(bal) - 1;
            bal &= bal - 1;
            long long base = (long long)(tok0 + bit) * 64;  // 64 float4 per row
            out4[base + lane]      = zero4;
            out4[base + 32 + lane] = zero4;
        }
        return;
    }

    // ---- per-bin stats + normalize path ----
    __shared__ int s_tok[CAP];
    int b = blockIdx.x;
    int cnt_raw = d_count[b];
    int cnt = cnt_raw < CAP ? cnt_raw : CAP;
    for (int j = tid; j < cnt; j += 128) s_tok[j] = d_tokenlist[b * CAP + j];
    __syncthreads();
    if (tid == 0) d_count[b] = 0;   // self-zero for next launch/replay

    const float2* patches2 = (const float2*)patches;
    float2*       out2     = (float2*)out;
    int idx = b * 128 + tid;        // float2 index into [NBINS, 128] stat rows
    float2 mo = ((const float2*)mean_in)[idx];

    float s1x = 0.f, s1y = 0.f, s2x = 0.f, s2y = 0.f;

    int k = 0;
    for (; k + 3 < cnt; k += 4) {
        int t0 = s_tok[k + 0], t1 = s_tok[k + 1];
        int t2 = s_tok[k + 2], t3 = s_tok[k + 3];
        float2 p0 = patches2[t0 * 128 + tid];
        float2 p1 = patches2[t1 * 128 + tid];
        float2 p2 = patches2[t2 * 128 + tid];
        float2 p3 = patches2[t3 * 128 + tid];
        float e0x = p0.x - mo.x, e0y = p0.y - mo.y;
        float e1x = p1.x - mo.x, e1y = p1.y - mo.y;
        float e2x = p2.x - mo.x, e2y = p2.y - mo.y;
        float e3x = p3.x - mo.x, e3y = p3.y - mo.y;
        s1x += e0x + e1x + e2x + e3x;
        s1y += e0y + e1y + e2y + e3y;
        s2x += e0x * e0x + e1x * e1x + e2x * e2x + e3x * e3x;
        s2y += e0y * e0y + e1y * e1y + e2y * e2y + e3y * e3y;
    }
    for (; k < cnt; k++) {
        float2 p = patches2[s_tok[k] * 128 + tid];
        float ex = p.x - mo.x, ey = p.y - mo.y;
        s1x += ex; s1y += ey;
        s2x += ex * ex; s2y += ey * ey;
    }

    float n_new = n_buf[b] + (float)cnt_raw;
    float nden  = fmaxf(n_new, 1.0f);
    float dx = s1x / nden, dy = s1y / nden;
    float mnx = mo.x + dx, mny = mo.y + dy;
    float2 m2v = ((const float2*)m2_in)[idx];
    float m2x = m2v.x + (s2x - dx * s1x);
    float m2y = m2v.y + (s2y - dy * s1y);
    float varx = m2x / nden, vary = m2y / nden;
    if (n_new < 2.0f) { varx = 1.0f; vary = 1.0f; }
    float invx = 1.0f / (sqrtf(varx) + EPS);
    float invy = 1.0f / (sqrtf(vary) + EPS);

    // pass 2: normalize (re-read is L2-hot) and write out
    k = 0;
    for (; k + 1 < cnt; k += 2) {
        int t0 = s_tok[k + 0], t1 = s_tok[k + 1];
        float2 p0 = patches2[t0 * 128 + tid];
        float2 p1 = patches2[t1 * 128 + tid];
        float2 r0, r1;
        r0.x = fminf(fmaxf((p0.x - mnx) * invx, MIN_VAL), MAX_VAL);
        r0.y = fminf(fmaxf((p0.y - mny) * invy, MIN_VAL), MAX_VAL);
        r1.x = fminf(fmaxf((p1.x - mnx) * invx, MIN_VAL), MAX_VAL);
        r1.y = fminf(fmaxf((p1.y - mny) * invy, MIN_VAL), MAX_VAL);
        out2[t0 * 128 + tid] = r0;
        out2[t1 * 128 + tid] = r1;
    }
    for (; k < cnt; k++) {
        int t0 = s_tok[k];
        float2 p = patches2[t0 * 128 + tid];
        float2 r;
        r.x = fminf(fmaxf((p.x - mnx) * invx, MIN_VAL), MAX_VAL);
        r.y = fminf(fmaxf((p.y - mny) * invy, MIN_VAL), MAX_VAL);
        out2[t0 * 128 + tid] = r;
    }
}

// ---------------- launch ----------------------------------------------------
extern "C" void kernel_launch(void* const* d_in, const int* in_sizes, int n_in,
                              void* d_out, int out_size) {
    const float*        patches = (const float*)d_in[0];
    const int*          pc      = (const int*)d_in[1];
    const int*          ph      = (const int*)d_in[2];
    const int*          pw      = (const int*)d_in[3];
    const unsigned int* mask    = (const unsigned int*)d_in[4];
    const float*        n_buf   = (const float*)d_in[5];
    const float*        mean_in = (const float*)d_in[6];
    const float*        m2_in   = (const float*)d_in[7];
    float*              out     = (float*)d_out;

    k_scatter<<<(NTOK + 255) / 256, 256>>>(pc, ph, pw, mask);
    k_fused<<<NBINS + PADBLKS, 128>>>(patches, mask, n_buf, mean_in, m2_in, out);
}

// round 15
// speedup vs baseline: 1.3677x; 1.1735x over previous
#include <cuda_runtime.h>
#include <cuda_bf16.h>

// Problem constants
#define C_DIM 3
#define H_DIM 32
#define W_DIM 32
#define Z_DIM 256
#define NTOK (128 * 1024)             // 131072 tokens
#define NBINS (C_DIM * H_DIM * W_DIM) // 3072 bins
#define CAP 192                       // max valid tokens per bin (mean ~21)
#define SCATBLKS 512                  // scatter blocks (256 thr, 1 token/thr)
#define PADBLKS 512                   // pad-zero blocks (256 thr = 8 warps)
#define EPS 1e-6f
#define MAX_VAL 5.0f
#define MIN_VAL (-5.0f)

// mask: 32-bit word per token (bool promoted by harness); nonzero == padded.

// ---------------- device scratch (static; no allocations allowed) ----------
// d_count starts zeroed (static init) and is re-zeroed by k_fused each launch.
__device__ int d_count[NBINS];
__device__ int d_tokenlist[NBINS * CAP];

// ---------------- K1: scatter + pad-zero (independent work, one launch) ----
// blocks [0, SCATBLKS): scatter valid token ids into per-bin slots.
// blocks [SCATBLKS, +PADBLKS): warp-per-32-token ballot scan; cooperative
//   1KB zero-fill of each padded token's output row. Independent of scatter.
__global__ __launch_bounds__(256) void k_scatter_pad(
        const int* __restrict__ pc,
        const int* __restrict__ ph,
        const int* __restrict__ pw,
        const unsigned int* __restrict__ mask,
        float* __restrict__ out) {
    int tid = threadIdx.x;

    if (blockIdx.x < SCATBLKS) {
        int i = blockIdx.x * 256 + tid;
        if (mask[i] == 0u) {
            int flat = pc[i] * (H_DIM * W_DIM) + ph[i] * W_DIM + pw[i];
            int pos = atomicAdd(&d_count[flat], 1);
            if (pos < CAP) d_tokenlist[flat * CAP + pos] = i;
        }
        return;
    }

    // ---- pad-zero path ----
    int warp = (blockIdx.x - SCATBLKS) * 8 + (tid >> 5); // global warp id
    int lane = tid & 31;
    int tok0 = warp * 32;                                 // 32 tokens per warp
    unsigned int m = mask[tok0 + lane];
    unsigned int bal = __ballot_sync(0xFFFFFFFFu, m != 0u);
    float4 zero4 = make_float4(0.f, 0.f, 0.f, 0.f);
    float4* out4 = (float4*)out;
    while (bal) {
        int bit = __ffs(bal) - 1;
        bal &= bal - 1;
        long long base = (long long)(tok0 + bit) * 64;    // 64 float4 per row
        out4[base + lane]      = zero4;
        out4[base + 32 + lane] = zero4;
    }
}

// ---------------- K2: per-bin stats + normalize ----------------------------
// One 128-thread block per bin; thread owns 2 features (float2).
//   pass 1: reduce S1,S2 over bin's valid rows (DRAM read, x8 unroll)
//   pass 2: re-read rows (L2-hot) and write normalized output (x4 unroll)
__global__ __launch_bounds__(128) void k_fused(
        const float* __restrict__ patches,
        const float* __restrict__ n_buf,
        const float* __restrict__ mean_in,
        const float* __restrict__ m2_in,
        float* __restrict__ out) {
    int tid = threadIdx.x;

    __shared__ int s_tok[CAP];
    int b = blockIdx.x;
    int cnt_raw = d_count[b];
    int cnt = cnt_raw < CAP ? cnt_raw : CAP;
    for (int j = tid; j < cnt; j += 128) s_tok[j] = d_tokenlist[b * CAP + j];
    __syncthreads();
    if (tid == 0) d_count[b] = 0;   // self-zero for next launch/replay

    const float2* patches2 = (const float2*)patches;
    float2*       out2     = (float2*)out;
    int idx = b * 128 + tid;        // float2 index into [NBINS, 128] stat rows
    float2 mo = ((const float2*)mean_in)[idx];

    float s1x = 0.f, s1y = 0.f, s2x = 0.f, s2y = 0.f;

    int k = 0;
    for (; k + 7 < cnt; k += 8) {
        float2 p0 = patches2[s_tok[k + 0] * 128 + tid];
        float2 p1 = patches2[s_tok[k + 1] * 128 + tid];
        float2 p2 = patches2[s_tok[k + 2] * 128 + tid];
        float2 p3 = patches2[s_tok[k + 3] * 128 + tid];
        float2 p4 = patches2[s_tok[k + 4] * 128 + tid];
        float2 p5 = patches2[s_tok[k + 5] * 128 + tid];
        float2 p6 = patches2[s_tok[k + 6] * 128 + tid];
        float2 p7 = patches2[s_tok[k + 7] * 128 + tid];
        float e0x = p0.x - mo.x, e0y = p0.y - mo.y;
        float e1x = p1.x - mo.x, e1y = p1.y - mo.y;
        float e2x = p2.x - mo.x, e2y = p2.y - mo.y;
        float e3x = p3.x - mo.x, e3y = p3.y - mo.y;
        float e4x = p4.x - mo.x, e4y = p4.y - mo.y;
        float e5x = p5.x - mo.x, e5y = p5.y - mo.y;
        float e6x = p6.x - mo.x, e6y = p6.y - mo.y;
        float e7x = p7.x - mo.x, e7y = p7.y - mo.y;
        s1x += (e0x + e1x) + (e2x + e3x) + (e4x + e5x) + (e6x + e7x);
        s1y += (e0y + e1y) + (e2y + e3y) + (e4y + e5y) + (e6y + e7y);
        s2x += (e0x * e0x + e1x * e1x) + (e2x * e2x + e3x * e3x)
             + (e4x * e4x + e5x * e5x) + (e6x * e6x + e7x * e7x);
        s2y += (e0y * e0y + e1y * e1y) + (e2y * e2y + e3y * e3y)
             + (e4y * e4y + e5y * e5y) + (e6y * e6y + e7y * e7y);
    }
    for (; k < cnt; k++) {
        float2 p = patches2[s_tok[k] * 128 + tid];
        float ex = p.x - mo.x, ey = p.y - mo.y;
        s1x += ex; s1y += ey;
        s2x += ex * ex; s2y += ey * ey;
    }

    float n_new = n_buf[b] + (float)cnt_raw;
    float nden  = fmaxf(n_new, 1.0f);
    float dx = s1x / nden, dy = s1y / nden;
    float mnx = mo.x + dx, mny = mo.y + dy;
    float2 m2v = ((const float2*)m2_in)[idx];
    float m2x = m2v.x + (s2x - dx * s1x);
    float m2y = m2v.y + (s2y - dy * s1y);
    float varx = m2x / nden, vary = m2y / nden;
    if (n_new < 2.0f) { varx = 1.0f; vary = 1.0f; }
    float invx = 1.0f / (sqrtf(varx) + EPS);
    float invy = 1.0f / (sqrtf(vary) + EPS);

    // pass 2: normalize (re-read is L2-hot) and write out
    k = 0;
    for (; k + 3 < cnt; k += 4) {
        int t0 = s_tok[k + 0], t1 = s_tok[k + 1];
        int t2 = s_tok[k + 2], t3 = s_tok[k + 3];
        float2 p0 = patches2[t0 * 128 + tid];
        float2 p1 = patches2[t1 * 128 + tid];
        float2 p2 = patches2[t2 * 128 + tid];
        float2 p3 = patches2[t3 * 128 + tid];
        float2 r0, r1, r2, r3;
        r0.x = fminf(fmaxf((p0.x - mnx) * invx, MIN_VAL), MAX_VAL);
        r0.y = fminf(fmaxf((p0.y - mny) * invy, MIN_VAL), MAX_VAL);
        r1.x = fminf(fmaxf((p1.x - mnx) * invx, MIN_VAL), MAX_VAL);
        r1.y = fminf(fmaxf((p1.y - mny) * invy, MIN_VAL), MAX_VAL);
        r2.x = fminf(fmaxf((p2.x - mnx) * invx, MIN_VAL), MAX_VAL);
        r2.y = fminf(fmaxf((p2.y - mny) * invy, MIN_VAL), MAX_VAL);
        r3.x = fminf(fmaxf((p3.x - mnx) * invx, MIN_VAL), MAX_VAL);
        r3.y = fminf(fmaxf((p3.y - mny) * invy, MIN_VAL), MAX_VAL);
        out2[t0 * 128 + tid] = r0;
        out2[t1 * 128 + tid] = r1;
        out2[t2 * 128 + tid] = r2;
        out2[t3 * 128 + tid] = r3;
    }
    for (; k < cnt; k++) {
        int t0 = s_tok[k];
        float2 p = patches2[t0 * 128 + tid];
        float2 r;
        r.x = fminf(fmaxf((p.x - mnx) * invx, MIN_VAL), MAX_VAL);
        r.y = fminf(fmaxf((p.y - mny) * invy, MIN_VAL), MAX_VAL);
        out2[t0 * 128 + tid] = r;
    }
}

// ---------------- launch ----------------------------------------------------
extern "C" void kernel_launch(void* const* d_in, const int* in_sizes, int n_in,
                              void* d_out, int out_size) {
    const float*        patches = (const float*)d_in[0];
    const int*          pc      = (const int*)d_in[1];
    const int*          ph      = (const int*)d_in[2];
    const int*          pw      = (const int*)d_in[3];
    const unsigned int* mask    = (const unsigned int*)d_in[4];
    const float*        n_buf   = (const float*)d_in[5];
    const float*        mean_in = (const float*)d_in[6];
    const float*        m2_in   = (const float*)d_in[7];
    float*              out     = (float*)d_out;

    k_scatter_pad<<<SCATBLKS + PADBLKS, 256>>>(pc, ph, pw, mask, out);
    k_fused<<<NBINS, 128>>>(patches, n_buf, mean_in, m2_in, out);
}